// round 5
// baseline (speedup 1.0000x reference)
#include <cuda_runtime.h>
#include <cuda_fp16.h>
#include <cstdint>
#include <cstddef>

// Problem: B=4096, P=10, LD=TD=512, DIN=2048, BP=40960
// out = [logits 4096x10][best_lane 4096x512][best_nghl 4096x512][best_ngh 4096x512]
// Toolchain compiles via compute_103 PTX -> NO sm_103a-only features.
// mma.sync.m16n8k16 + cp.async. Concat+f32->f16 fused into GEMM1 A-path.

__device__ __align__(16) __half g_W1t[512 * 2048];        // W1^T fp16 [n][k]
__device__ __align__(16) __half g_embh[40960u * 512];     // relu(ctx@W1+b1) fp16 (= [4096][5120])
__device__ __align__(16) __half g_W2h[16 * 5120];         // W2^T padded fp16 [n16][k5120]

#define SW128(o) ((o) ^ (((o) >> 3) & 0x70))

__device__ __forceinline__ uint32_t smem_u32(const void* p) {
    uint32_t a;
    asm("{ .reg .u64 t; cvta.to.shared.u64 t, %1; cvt.u32.u64 %0, t; }" : "=r"(a) : "l"(p));
    return a;
}
__device__ __forceinline__ uint32_t pack_h2(float a, float b) {
    __half2 h = __floats2half2_rn(a, b);
    return *reinterpret_cast<uint32_t*>(&h);
}

#define CP16(dst, src) \
    asm volatile("cp.async.cg.shared.global [%0], [%1], 16;" :: "r"(dst), "l"(src) : "memory")
#define CP_COMMIT() asm volatile("cp.async.commit_group;" ::: "memory")
#define CP_WAIT2()  asm volatile("cp.async.wait_group 2;" ::: "memory")
#define CP_WAIT0()  asm volatile("cp.async.wait_group 0;" ::: "memory")

#define LDSM_X4(r, addr)                                                          \
    asm volatile("ldmatrix.sync.aligned.m8n8.x4.shared.b16 {%0,%1,%2,%3}, [%4];"  \
        : "=r"((r)[0]), "=r"((r)[1]), "=r"((r)[2]), "=r"((r)[3]) : "r"(addr))

#define MMA16816(d, a, b0, b1)                                                    \
    asm volatile("mma.sync.aligned.m16n8k16.row.col.f32.f16.f16.f32 "             \
        "{%0,%1,%2,%3}, {%4,%5,%6,%7}, {%8,%9}, {%0,%1,%2,%3};"                    \
        : "+f"((d)[0]), "+f"((d)[1]), "+f"((d)[2]), "+f"((d)[3])                   \
        : "r"((a)[0]), "r"((a)[1]), "r"((a)[2]), "r"((a)[3]), "r"(b0), "r"(b1))

// ---------------- Kernel 1: W1[2048,512] f32 -> W1t[512][2048] f16 ----------------
__global__ void w1t_kernel(const float* __restrict__ W1) {
    __shared__ float t[32][33];
    int kk = blockIdx.x * 32, nn = blockIdx.y * 32;
    int tx = threadIdx.x, ty = threadIdx.y;  // 32 x 8
#pragma unroll
    for (int q = 0; q < 4; q++)
        t[ty + 8 * q][tx] = W1[(size_t)(kk + ty + 8 * q) * 512 + nn + tx];
    __syncthreads();
#pragma unroll
    for (int q = 0; q < 4; q++)
        g_W1t[(size_t)(nn + ty + 8 * q) * 2048 + kk + tx] = __float2half(t[tx][ty + 8 * q]);
}

// ---------------- Kernel 2: W2 -> fp16 padded (idx<81920) + logits=b2 (else) -------
__global__ void __launch_bounds__(256) prep2_kernel(const float* __restrict__ W2,
                                                    const float* __restrict__ b2,
                                                    float* __restrict__ logits) {
    int idx = blockIdx.x * 256 + threadIdx.x;      // 122880
    if (idx < 81920) {
        int n = idx / 5120, k = idx % 5120;
        g_W2h[idx] = __float2half(n < 10 ? W2[(size_t)k * 10 + n] : 0.0f);
    } else {
        int j = idx - 81920;                       // 40960
        logits[j] = __ldg(b2 + j % 10);
    }
}

// ---------------- Kernel 3: GEMM1 emb = relu(concat(ctx) @ W1 + b1) ----------------
// CTA 128m x 256n, 8 warps (2m x 4n), warp 64x64, K-chunk 64.
// A: LDG f32 (4 src tensors, fused concat) -> cvt f16 -> STS (2 SMEM bufs).
// B: cp.async fp16, 4 stages.
#define B_STAGES  4
#define A_BUF_SZ  16384                    // 128 rows x 128B
#define B_STAGE   32768                    // 256 rows x 128B
#define G1_SMEM   (2 * A_BUF_SZ + B_STAGES * B_STAGE)   // 163840

__global__ void __launch_bounds__(256, 1) gemm1_kernel(
    const float* __restrict__ agent, const float* __restrict__ lanec,
    const float* __restrict__ nghl,  const float* __restrict__ ngh,
    const float* __restrict__ b1)
{
    extern __shared__ char sm[];
    const uint32_t sA = smem_u32(sm);
    const uint32_t sB = sA + 2 * A_BUF_SZ;
    const int t = threadIdx.x;
    const int n0 = blockIdx.x * 256;
    const int m0 = blockIdx.y * 128;
    const __half* gB = g_W1t + (size_t)n0 * 2048;

    // --- A-side (fused concat, f32 -> f16): 2 threads/row, 32 f32 each ---
    const int r = t >> 1;
    const int csub = (t & 1) << 5;
    const int grow = m0 + r;
    const float* srcs[4] = {
        agent + (size_t)(grow / 10) * 512 + csub,
        lanec + (size_t)grow * 512 + csub,
        nghl  + (size_t)grow * 512 + csub,
        ngh   + (size_t)grow * 512 + csub };
    const int abase = r * 128 + (csub << 1);  // byte offset in A tile

    // --- B-side cp.async addressing ---
    const int lrow = t >> 3, lcu = t & 7;

    const int warp = t >> 5, ln = t & 31;
    const int wm = warp & 1, wn = warp >> 1;
    const int a_row = (ln & 7) + ((ln >> 3) & 1) * 8;
    const int a_kb  = (ln >> 4) << 4;
    const uint32_t aBase = (uint32_t)(wm * 64 + a_row) * 128 + a_kb;
    const int b_row = (ln & 7) + ((ln >> 4) << 3);
    const int b_kb  = ((ln >> 3) & 1) << 4;
    const uint32_t bBase = (uint32_t)(wn * 64 + b_row) * 128 + b_kb;

    float d[4][8][4];
#pragma unroll
    for (int mf = 0; mf < 4; mf++)
#pragma unroll
        for (int nf = 0; nf < 8; nf++)
#pragma unroll
            for (int q = 0; q < 4; q++) d[mf][nf][q] = 0.0f;

    float4 ra[8];
    auto ldgA = [&](int c) {
        const float* ap = srcs[c >> 3] + ((c & 7) << 6);
#pragma unroll
        for (int i = 0; i < 8; i++) ra[i] = __ldg((const float4*)ap + i);
    };
    auto stsA = [&](int buf) {
        char* A = sm + buf * A_BUF_SZ;
#pragma unroll
        for (int i = 0; i < 4; i++) {
            float4 lo = ra[2 * i], hi = ra[2 * i + 1];
            uint4 v;
            v.x = pack_h2(lo.x, lo.y); v.y = pack_h2(lo.z, lo.w);
            v.z = pack_h2(hi.x, hi.y); v.w = pack_h2(hi.z, hi.w);
            *(uint4*)(A + SW128(abase + i * 16)) = v;
        }
    };
    auto ldB = [&](int c, int slot) {
        const int k0 = c * 64;
#pragma unroll
        for (int i = 0; i < 8; i++) {
            int row = lrow + 32 * i;
            uint32_t dst = sB + slot * B_STAGE + SW128(row * 128 + lcu * 16);
            CP16(dst, gB + (size_t)row * 2048 + k0 + lcu * 8);
        }
    };

    // prologue: A chunk0 staged; B chunks 0..2 in flight
    ldgA(0);
    stsA(0);
#pragma unroll
    for (int s = 0; s < B_STAGES - 1; s++) { ldB(s, s); CP_COMMIT(); }

    for (int c = 0; c < 32; c++) {
        CP_WAIT2();
        __syncthreads();                       // B(c) ready; A(c) visible
        if (c + 1 < 32) ldgA(c + 1);
        if (c + B_STAGES - 1 < 32) ldB(c + B_STAGES - 1, (c + B_STAGES - 1) & 3);
        CP_COMMIT();

        const uint32_t slotA = sA + (c & 1) * A_BUF_SZ;
        const uint32_t slotB = sB + (c & 3) * B_STAGE;
#pragma unroll
        for (int s = 0; s < 4; s++) {
            uint32_t a[4][4], bb[4][4];
#pragma unroll
            for (int mf = 0; mf < 4; mf++)
                LDSM_X4(a[mf], slotA + SW128(aBase + mf * 2048 + s * 32));
#pragma unroll
            for (int nb = 0; nb < 4; nb++)
                LDSM_X4(bb[nb], slotB + SW128(bBase + nb * 2048 + s * 32));
#pragma unroll
            for (int mf = 0; mf < 4; mf++)
#pragma unroll
                for (int nf = 0; nf < 8; nf++) {
                    const int nb = nf >> 1, h = (nf & 1) * 2;
                    MMA16816(d[mf][nf], a[mf], bb[nb][h], bb[nb][h + 1]);
                }
        }
        if (c + 1 < 32) stsA((c + 1) & 1);     // write other A buffer
        __syncthreads();
    }
    CP_WAIT0();

    const int gid = ln >> 2, tc = (ln & 3) * 2;
#pragma unroll
    for (int nf = 0; nf < 8; nf++) {
        const int col = n0 + wn * 64 + nf * 8 + tc;
        float2 bv = __ldg((const float2*)(b1 + col));
#pragma unroll
        for (int mf = 0; mf < 4; mf++) {
            const int r0 = m0 + wm * 64 + mf * 16 + gid;
            float* dd = d[mf][nf];
            __half2 h0 = __floats2half2_rn(fmaxf(dd[0] + bv.x, 0.0f), fmaxf(dd[1] + bv.y, 0.0f));
            __half2 h1 = __floats2half2_rn(fmaxf(dd[2] + bv.x, 0.0f), fmaxf(dd[3] + bv.y, 0.0f));
            *(__half2*)(g_embh + (size_t)r0 * 512 + col) = h0;
            *(__half2*)(g_embh + (size_t)(r0 + 8) * 512 + col) = h1;
        }
    }
}

// ---------------- Kernel 4: GEMM2 logits += emb[4096,5120] @ W2h^T --------------
#define G2_STAGES  4
#define G2_A_STAGE 16384                   // 128 x 128B
#define G2_B_STAGE 2048                    // 16 x 128B
#define G2_SMEM    (G2_STAGES * (G2_A_STAGE + G2_B_STAGE))  // 73728

__global__ void __launch_bounds__(256, 1) gemm2_kernel(float* __restrict__ logits) {
    extern __shared__ char sm[];
    const uint32_t sA = smem_u32(sm);
    const uint32_t sB = sA + G2_STAGES * G2_A_STAGE;
    const int t = threadIdx.x;
    const int m0 = blockIdx.x * 128;
    const int kbase = blockIdx.y * 1280;
    const __half* gA = g_embh + (size_t)m0 * 5120 + kbase;
    const __half* gB = g_W2h + kbase;

    const int lrow = t >> 3, lcu = t & 7;
    const int warp = t >> 5, ln = t & 31;
    const int a_row = (ln & 7) + ((ln >> 3) & 1) * 8;
    const int a_kb  = (ln >> 4) << 4;
    const uint32_t aBase = (uint32_t)(warp * 16 + a_row) * 128 + a_kb;
    const int b_row = (ln & 7) + ((ln >> 4) << 3);
    const int b_kb  = ((ln >> 3) & 1) << 4;
    const uint32_t bBase = (uint32_t)b_row * 128 + b_kb;

    float d[2][4];
#pragma unroll
    for (int nf = 0; nf < 2; nf++)
#pragma unroll
        for (int q = 0; q < 4; q++) d[nf][q] = 0.0f;

    auto load_stage = [&](int c, int slot) {
        const int k0 = c * 64;
#pragma unroll
        for (int i = 0; i < 4; i++) {
            int row = lrow + 32 * i;
            uint32_t dst = sA + slot * G2_A_STAGE + SW128(row * 128 + lcu * 16);
            CP16(dst, gA + (size_t)row * 5120 + k0 + lcu * 8);
        }
        if (t < 128) {
            int row = t >> 3;
            uint32_t dst = sB + slot * G2_B_STAGE + SW128(row * 128 + lcu * 16);
            CP16(dst, gB + (size_t)row * 5120 + k0 + lcu * 8);
        }
    };

#pragma unroll
    for (int s = 0; s < G2_STAGES - 1; s++) { load_stage(s, s); CP_COMMIT(); }

    for (int c = 0; c < 20; c++) {
        CP_WAIT2();
        __syncthreads();
        if (c + G2_STAGES - 1 < 20) load_stage(c + G2_STAGES - 1, (c + G2_STAGES - 1) & 3);
        CP_COMMIT();

        const uint32_t slotA = sA + (c & 3) * G2_A_STAGE;
        const uint32_t slotB = sB + (c & 3) * G2_B_STAGE;
#pragma unroll
        for (int s = 0; s < 4; s++) {
            uint32_t a[4], bb[4];
            LDSM_X4(a, slotA + SW128(aBase + s * 32));
            LDSM_X4(bb, slotB + SW128(bBase + s * 32));
            MMA16816(d[0], a, bb[0], bb[1]);
            MMA16816(d[1], a, bb[2], bb[3]);
        }
        __syncthreads();
    }
    CP_WAIT0();

    const int gid = ln >> 2, tc = (ln & 3) * 2;
#pragma unroll
    for (int nf = 0; nf < 2; nf++)
#pragma unroll
        for (int q = 0; q < 4; q++) {
            int col = nf * 8 + tc + (q & 1);
            int row = m0 + warp * 16 + gid + (q >> 1) * 8;
            if (col < 10) atomicAdd(&logits[(size_t)row * 10 + col], d[nf][q]);
        }
}

// ---------------- Kernel 5: gather best_* by one-hot label ----------------
__global__ void gather_kernel(const float* __restrict__ lanec, const float* __restrict__ nghl,
                              const float* __restrict__ ngh, const int* __restrict__ label,
                              float* __restrict__ out) {
    int b = blockIdx.x, tid = threadIdx.x;
    __shared__ int sidx;
    if (tid < 10 && label[b * 10 + tid] == 1) sidx = tid;
    __syncthreads();
    size_t src = ((size_t)b * 10 + sidx) * 512;
    float4 v1 = ((const float4*)(lanec + src))[tid];
    float4 v2 = ((const float4*)(nghl + src))[tid];
    float4 v3 = ((const float4*)(ngh + src))[tid];
    ((float4*)(out + 40960 + (size_t)b * 512))[tid] = v1;
    ((float4*)(out + 40960 + 2097152 + (size_t)b * 512))[tid] = v2;
    ((float4*)(out + 40960 + 4194304 + (size_t)b * 512))[tid] = v3;
}

// ---------------- launch ----------------
extern "C" void kernel_launch(void* const* d_in, const int* in_sizes, int n_in,
                              void* d_out, int out_size) {
    const float* agent = (const float*)d_in[0];
    const float* lanec = (const float*)d_in[1];
    const float* nghl  = (const float*)d_in[2];
    const float* ngh   = (const float*)d_in[3];
    const int*   label = (const int*)d_in[4];
    const float* W1    = (const float*)d_in[5];
    const float* b1    = (const float*)d_in[6];
    const float* W2    = (const float*)d_in[7];
    const float* b2    = (const float*)d_in[8];
    float* out = (float*)d_out;

    cudaFuncSetAttribute(gemm1_kernel, cudaFuncAttributeMaxDynamicSharedMemorySize, G1_SMEM);
    cudaFuncSetAttribute(gemm2_kernel, cudaFuncAttributeMaxDynamicSharedMemorySize, G2_SMEM);

    w1t_kernel<<<dim3(64, 16), dim3(32, 8)>>>(W1);
    prep2_kernel<<<480, 256>>>(W2, b2, out);
    gemm1_kernel<<<dim3(2, 320), 256, G1_SMEM>>>(agent, lanec, nghl, ngh, b1);
    gemm2_kernel<<<dim3(32, 4), 256, G2_SMEM>>>(out);
    gather_kernel<<<4096, 128>>>(lanec, nghl, ngh, label, out);
}

// round 6
// speedup vs baseline: 1.3191x; 1.3191x over previous
#include <cuda_runtime.h>
#include <cuda_fp16.h>
#include <cstdint>
#include <cstddef>

// Problem: B=4096, P=10, LD=TD=512, DIN=2048, BP=40960
// out = [logits 4096x10][best_lane 4096x512][best_nghl 4096x512][best_ngh 4096x512]
// compute_103 PTX -> legacy mma.sync.m16n8k16 + cp.async only.
// Split GEMM1: ctx@W1 = agent@W1a (per-batch, x10 smaller) + [lane|nghl|ngh]@W1bcd.

__device__ __align__(16) __half g_W1t[512 * 2048];       // W1^T fp16 [n][k]
__device__ __align__(16) __half g_laneh[40960u * 512];   // lane fp16
__device__ __align__(16) __half g_nghlh[40960u * 512];   // nghl fp16
__device__ __align__(16) __half g_nghh[40960u * 512];    // ngh fp16
__device__ __align__(16) __half g_agenth[4096u * 512];   // agent fp16
__device__ __align__(16) float  g_agw[4096u * 512];      // agent@W1a + b1 (fp32)
__device__ __align__(16) __half g_embh[40960u * 512];    // relu(...) fp16 (= [4096][5120])
__device__ __align__(16) __half g_W2h[16 * 5120];        // W2^T padded fp16 [n16][k5120]

#define SW128(o) ((o) ^ (((o) >> 3) & 0x70))

__device__ __forceinline__ uint32_t smem_u32(const void* p) {
    uint32_t a;
    asm("{ .reg .u64 t; cvta.to.shared.u64 t, %1; cvt.u32.u64 %0, t; }" : "=r"(a) : "l"(p));
    return a;
}
__device__ __forceinline__ uint32_t pack_h2(float a, float b) {
    __half2 h = __floats2half2_rn(a, b);
    return *reinterpret_cast<uint32_t*>(&h);
}

#define CP16(dst, src) \
    asm volatile("cp.async.cg.shared.global [%0], [%1], 16;" :: "r"(dst), "l"(src) : "memory")
#define CP_COMMIT() asm volatile("cp.async.commit_group;" ::: "memory")
#define CP_WAIT2()  asm volatile("cp.async.wait_group 2;" ::: "memory")
#define CP_WAIT0()  asm volatile("cp.async.wait_group 0;" ::: "memory")

#define LDSM_X4(r, addr)                                                          \
    asm volatile("ldmatrix.sync.aligned.m8n8.x4.shared.b16 {%0,%1,%2,%3}, [%4];"  \
        : "=r"((r)[0]), "=r"((r)[1]), "=r"((r)[2]), "=r"((r)[3]) : "r"(addr))

#define MMA16816(d, a, b0, b1)                                                    \
    asm volatile("mma.sync.aligned.m16n8k16.row.col.f32.f16.f16.f32 "             \
        "{%0,%1,%2,%3}, {%4,%5,%6,%7}, {%8,%9}, {%0,%1,%2,%3};"                    \
        : "+f"((d)[0]), "+f"((d)[1]), "+f"((d)[2]), "+f"((d)[3])                   \
        : "r"((a)[0]), "r"((a)[1]), "r"((a)[2]), "r"((a)[3]), "r"(b0), "r"(b1))

// ---------------- Kernel 1: W1[2048,512] f32 -> W1t[512][2048] f16 ----------------
__global__ void w1t_kernel(const float* __restrict__ W1) {
    __shared__ float t[32][33];
    int kk = blockIdx.x * 32, nn = blockIdx.y * 32;
    int tx = threadIdx.x, ty = threadIdx.y;  // 32 x 8
#pragma unroll
    for (int q = 0; q < 4; q++)
        t[ty + 8 * q][tx] = W1[(size_t)(kk + ty + 8 * q) * 512 + nn + tx];
    __syncthreads();
#pragma unroll
    for (int q = 0; q < 4; q++)
        g_W1t[(size_t)(nn + ty + 8 * q) * 2048 + kk + tx] = __float2half(t[tx][ty + 8 * q]);
}

// ---------------- Kernel 2: per-row f32->f16 convert + fused gather ----------------
__global__ void __launch_bounds__(128) prep_rows_kernel(
    const float* __restrict__ lanec, const float* __restrict__ nghl,
    const float* __restrict__ ngh,   const float* __restrict__ agent,
    const int* __restrict__ label,   float* __restrict__ out)
{
    const int row = blockIdx.x;            // 0..40959
    const int t = threadIdx.x;             // 128
    const size_t src = (size_t)row * 512 + t * 4;
    float4 v1 = __ldg((const float4*)(lanec + src));
    float4 v2 = __ldg((const float4*)(nghl + src));
    float4 v3 = __ldg((const float4*)(ngh + src));
    uint2 o1 = { pack_h2(v1.x, v1.y), pack_h2(v1.z, v1.w) };
    uint2 o2 = { pack_h2(v2.x, v2.y), pack_h2(v2.z, v2.w) };
    uint2 o3 = { pack_h2(v3.x, v3.y), pack_h2(v3.z, v3.w) };
    *(uint2*)(g_laneh + src) = o1;
    *(uint2*)(g_nghlh + src) = o2;
    *(uint2*)(g_nghh + src) = o3;
    if (__ldg(label + row) == 1) {         // fused gather (one row per batch)
        size_t b = row / 10;
        size_t dst = b * 512 + t * 4;
        *(float4*)(out + 40960 + dst) = v1;
        *(float4*)(out + 40960 + 2097152 + dst) = v2;
        *(float4*)(out + 40960 + 4194304 + dst) = v3;
    }
    if (row % 10 == 0) {                   // agent conversion once per batch
        size_t b = row / 10;
        float4 va = __ldg((const float4*)(agent + b * 512 + t * 4));
        uint2 oa = { pack_h2(va.x, va.y), pack_h2(va.z, va.w) };
        *(uint2*)(g_agenth + b * 512 + t * 4) = oa;
    }
}

// ---------------- Kernel 3: W2 -> fp16 padded + logits init = b2 ----------------
__global__ void __launch_bounds__(256) prep2_kernel(const float* __restrict__ W2,
                                                    const float* __restrict__ b2,
                                                    float* __restrict__ logits) {
    int idx = blockIdx.x * 256 + threadIdx.x;      // 122880
    if (idx < 81920) {
        int n = idx / 5120, k = idx % 5120;
        g_W2h[idx] = __float2half(n < 10 ? W2[(size_t)k * 10 + n] : 0.0f);
    } else {
        int j = idx - 81920;                       // 40960
        logits[j] = __ldg(b2 + j % 10);
    }
}

// ---------------- shared GEMM tile config (128m x 256n, 8 warps) ----------------
#define STAGES    4
#define A_STAGE   16384                    // 128 rows x 128B
#define B_STAGE   32768                    // 256 rows x 128B
#define G1_SMEM   (STAGES * (A_STAGE + B_STAGE))   // 196608

// ---------------- Kernel 4: agemm  g_agw = agent@W1a + b1 (fp32) ----------------
__global__ void __launch_bounds__(256, 1) agemm_kernel(const float* __restrict__ b1) {
    extern __shared__ char sm[];
    const uint32_t sA = smem_u32(sm);
    const uint32_t sB = sA + STAGES * A_STAGE;
    const int t = threadIdx.x;
    const int n0 = blockIdx.x * 256;
    const int m0 = blockIdx.y * 128;
    const __half* gA = g_agenth + (size_t)m0 * 512;
    const __half* gB = g_W1t + (size_t)n0 * 2048;   // k offset 0..511 = agent block

    const int lrow = t >> 3, lcu = t & 7;
    const int warp = t >> 5, ln = t & 31;
    const int wm = warp & 1, wn = warp >> 1;
    const int a_row = (ln & 7) + ((ln >> 3) & 1) * 8;
    const int a_kb  = (ln >> 4) << 4;
    const uint32_t aBase = (uint32_t)(wm * 64 + a_row) * 128 + a_kb;
    const int b_row = (ln & 7) + ((ln >> 4) << 3);
    const int b_kb  = ((ln >> 3) & 1) << 4;
    const uint32_t bBase = (uint32_t)(wn * 64 + b_row) * 128 + b_kb;

    float d[4][8][4];
#pragma unroll
    for (int mf = 0; mf < 4; mf++)
#pragma unroll
        for (int nf = 0; nf < 8; nf++)
#pragma unroll
            for (int q = 0; q < 4; q++) d[mf][nf][q] = 0.0f;

    auto load_stage = [&](int c, int slot) {
        const int k0 = c * 64;
#pragma unroll
        for (int i = 0; i < 4; i++) {
            int row = lrow + 32 * i;
            uint32_t dst = sA + slot * A_STAGE + SW128(row * 128 + lcu * 16);
            CP16(dst, gA + (size_t)row * 512 + k0 + lcu * 8);
        }
#pragma unroll
        for (int i = 0; i < 8; i++) {
            int row = lrow + 32 * i;
            uint32_t dst = sB + slot * B_STAGE + SW128(row * 128 + lcu * 16);
            CP16(dst, gB + (size_t)row * 2048 + k0 + lcu * 8);
        }
    };

#pragma unroll
    for (int s = 0; s < STAGES - 1; s++) { load_stage(s, s); CP_COMMIT(); }

    for (int c = 0; c < 8; c++) {
        CP_WAIT2();
        __syncthreads();
        if (c + STAGES - 1 < 8) load_stage(c + STAGES - 1, (c + STAGES - 1) & 3);
        CP_COMMIT();
        const uint32_t slotA = sA + (c & 3) * A_STAGE;
        const uint32_t slotB = sB + (c & 3) * B_STAGE;
#pragma unroll
        for (int s = 0; s < 4; s++) {
            uint32_t a[4][4], bb[4][4];
#pragma unroll
            for (int mf = 0; mf < 4; mf++)
                LDSM_X4(a[mf], slotA + SW128(aBase + mf * 2048 + s * 32));
#pragma unroll
            for (int nb = 0; nb < 4; nb++)
                LDSM_X4(bb[nb], slotB + SW128(bBase + nb * 2048 + s * 32));
#pragma unroll
            for (int mf = 0; mf < 4; mf++)
#pragma unroll
                for (int nf = 0; nf < 8; nf++) {
                    const int nb = nf >> 1, h = (nf & 1) * 2;
                    MMA16816(d[mf][nf], a[mf], bb[nb][h], bb[nb][h + 1]);
                }
        }
        __syncthreads();
    }
    CP_WAIT0();

    const int gid = ln >> 2, tc = (ln & 3) * 2;
#pragma unroll
    for (int nf = 0; nf < 8; nf++) {
        const int col = n0 + wn * 64 + nf * 8 + tc;
        float2 bv = __ldg((const float2*)(b1 + col));
#pragma unroll
        for (int mf = 0; mf < 4; mf++) {
            const int r0 = m0 + wm * 64 + mf * 16 + gid;
            float* dd = d[mf][nf];
            float2 s0 = { dd[0] + bv.x, dd[1] + bv.y };
            float2 s1 = { dd[2] + bv.x, dd[3] + bv.y };
            *(float2*)(g_agw + (size_t)r0 * 512 + col) = s0;
            *(float2*)(g_agw + (size_t)(r0 + 8) * 512 + col) = s1;
        }
    }
}

// ---------------- Kernel 5: GEMM1 emb = relu(agw[b] + [lane|nghl|ngh]@W1bcd) -------
__global__ void __launch_bounds__(256, 1) gemm1_kernel() {
    extern __shared__ char sm[];
    const uint32_t sA = smem_u32(sm);
    const uint32_t sB = sA + STAGES * A_STAGE;
    const int t = threadIdx.x;
    const int n0 = blockIdx.x * 256;
    const int m0 = blockIdx.y * 128;
    const __half* gB = g_W1t + (size_t)n0 * 2048 + 512;  // k range 512..2048

    const int lrow = t >> 3, lcu = t & 7;
    const int warp = t >> 5, ln = t & 31;
    const int wm = warp & 1, wn = warp >> 1;
    const int a_row = (ln & 7) + ((ln >> 3) & 1) * 8;
    const int a_kb  = (ln >> 4) << 4;
    const uint32_t aBase = (uint32_t)(wm * 64 + a_row) * 128 + a_kb;
    const int b_row = (ln & 7) + ((ln >> 4) << 3);
    const int b_kb  = ((ln >> 3) & 1) << 4;
    const uint32_t bBase = (uint32_t)(wn * 64 + b_row) * 128 + b_kb;

    float d[4][8][4];
#pragma unroll
    for (int mf = 0; mf < 4; mf++)
#pragma unroll
        for (int nf = 0; nf < 8; nf++)
#pragma unroll
            for (int q = 0; q < 4; q++) d[mf][nf][q] = 0.0f;

    auto load_stage = [&](int c, int slot) {
        const __half* gA;
        if (c < 8)       gA = g_laneh + (size_t)m0 * 512;
        else if (c < 16) gA = g_nghlh + (size_t)m0 * 512;
        else             gA = g_nghh + (size_t)m0 * 512;
        const int k0 = (c & 7) * 64;
#pragma unroll
        for (int i = 0; i < 4; i++) {
            int row = lrow + 32 * i;
            uint32_t dst = sA + slot * A_STAGE + SW128(row * 128 + lcu * 16);
            CP16(dst, gA + (size_t)row * 512 + k0 + lcu * 8);
        }
        const int kb0 = c * 64;
#pragma unroll
        for (int i = 0; i < 8; i++) {
            int row = lrow + 32 * i;
            uint32_t dst = sB + slot * B_STAGE + SW128(row * 128 + lcu * 16);
            CP16(dst, gB + (size_t)row * 2048 + kb0 + lcu * 8);
        }
    };

#pragma unroll
    for (int s = 0; s < STAGES - 1; s++) { load_stage(s, s); CP_COMMIT(); }

    for (int c = 0; c < 24; c++) {
        CP_WAIT2();
        __syncthreads();
        if (c + STAGES - 1 < 24) load_stage(c + STAGES - 1, (c + STAGES - 1) & 3);
        CP_COMMIT();
        const uint32_t slotA = sA + (c & 3) * A_STAGE;
        const uint32_t slotB = sB + (c & 3) * B_STAGE;
#pragma unroll
        for (int s = 0; s < 4; s++) {
            uint32_t a[4][4], bb[4][4];
#pragma unroll
            for (int mf = 0; mf < 4; mf++)
                LDSM_X4(a[mf], slotA + SW128(aBase + mf * 2048 + s * 32));
#pragma unroll
            for (int nb = 0; nb < 4; nb++)
                LDSM_X4(bb[nb], slotB + SW128(bBase + nb * 2048 + s * 32));
#pragma unroll
            for (int mf = 0; mf < 4; mf++)
#pragma unroll
                for (int nf = 0; nf < 8; nf++) {
                    const int nb = nf >> 1, h = (nf & 1) * 2;
                    MMA16816(d[mf][nf], a[mf], bb[nb][h], bb[nb][h + 1]);
                }
        }
        __syncthreads();
    }
    CP_WAIT0();

    const int gid = ln >> 2, tc = (ln & 3) * 2;
#pragma unroll
    for (int nf = 0; nf < 8; nf++) {
        const int col = n0 + wn * 64 + nf * 8 + tc;
#pragma unroll
        for (int mf = 0; mf < 4; mf++) {
            const int r0 = m0 + wm * 64 + mf * 16 + gid;
            float* dd = d[mf][nf];
            float2 a0 = __ldg((const float2*)(g_agw + (size_t)(r0 / 10) * 512 + col));
            float2 a1 = __ldg((const float2*)(g_agw + (size_t)((r0 + 8) / 10) * 512 + col));
            __half2 h0 = __floats2half2_rn(fmaxf(dd[0] + a0.x, 0.0f), fmaxf(dd[1] + a0.y, 0.0f));
            __half2 h1 = __floats2half2_rn(fmaxf(dd[2] + a1.x, 0.0f), fmaxf(dd[3] + a1.y, 0.0f));
            *(__half2*)(g_embh + (size_t)r0 * 512 + col) = h0;
            *(__half2*)(g_embh + (size_t)(r0 + 8) * 512 + col) = h1;
        }
    }
}

// ---------------- Kernel 6: GEMM2 logits += emb[4096,5120] @ W2h^T --------------
#define G2_STAGES  4
#define G2_A_STAGE 16384
#define G2_B_STAGE 2048
#define G2_SMEM    (G2_STAGES * (G2_A_STAGE + G2_B_STAGE))  // 73728

__global__ void __launch_bounds__(256, 1) gemm2_kernel(float* __restrict__ logits) {
    extern __shared__ char sm[];
    const uint32_t sA = smem_u32(sm);
    const uint32_t sB = sA + G2_STAGES * G2_A_STAGE;
    const int t = threadIdx.x;
    const int m0 = blockIdx.x * 128;
    const int kbase = blockIdx.y * 1280;
    const __half* gA = g_embh + (size_t)m0 * 5120 + kbase;
    const __half* gB = g_W2h + kbase;

    const int lrow = t >> 3, lcu = t & 7;
    const int warp = t >> 5, ln = t & 31;
    const int a_row = (ln & 7) + ((ln >> 3) & 1) * 8;
    const int a_kb  = (ln >> 4) << 4;
    const uint32_t aBase = (uint32_t)(warp * 16 + a_row) * 128 + a_kb;
    const int b_row = (ln & 7) + ((ln >> 4) << 3);
    const int b_kb  = ((ln >> 3) & 1) << 4;
    const uint32_t bBase = (uint32_t)b_row * 128 + b_kb;

    float d[2][4];
#pragma unroll
    for (int nf = 0; nf < 2; nf++)
#pragma unroll
        for (int q = 0; q < 4; q++) d[nf][q] = 0.0f;

    auto load_stage = [&](int c, int slot) {
        const int k0 = c * 64;
#pragma unroll
        for (int i = 0; i < 4; i++) {
            int row = lrow + 32 * i;
            uint32_t dst = sA + slot * G2_A_STAGE + SW128(row * 128 + lcu * 16);
            CP16(dst, gA + (size_t)row * 5120 + k0 + lcu * 8);
        }
        if (t < 128) {
            int row = t >> 3;
            uint32_t dst = sB + slot * G2_B_STAGE + SW128(row * 128 + lcu * 16);
            CP16(dst, gB + (size_t)row * 5120 + k0 + lcu * 8);
        }
    };

#pragma unroll
    for (int s = 0; s < G2_STAGES - 1; s++) { load_stage(s, s); CP_COMMIT(); }

    for (int c = 0; c < 20; c++) {
        CP_WAIT2();
        __syncthreads();
        if (c + G2_STAGES - 1 < 20) load_stage(c + G2_STAGES - 1, (c + G2_STAGES - 1) & 3);
        CP_COMMIT();
        const uint32_t slotA = sA + (c & 3) * G2_A_STAGE;
        const uint32_t slotB = sB + (c & 3) * G2_B_STAGE;
#pragma unroll
        for (int s = 0; s < 4; s++) {
            uint32_t a[4], bb[4];
            LDSM_X4(a, slotA + SW128(aBase + s * 32));
            LDSM_X4(bb, slotB + SW128(bBase + s * 32));
            MMA16816(d[0], a, bb[0], bb[1]);
            MMA16816(d[1], a, bb[2], bb[3]);
        }
        __syncthreads();
    }
    CP_WAIT0();

    const int gid = ln >> 2, tc = (ln & 3) * 2;
#pragma unroll
    for (int nf = 0; nf < 2; nf++)
#pragma unroll
        for (int q = 0; q < 4; q++) {
            int col = nf * 8 + tc + (q & 1);
            int row = m0 + warp * 16 + gid + (q >> 1) * 8;
            if (col < 10) atomicAdd(&logits[(size_t)row * 10 + col], d[nf][q]);
        }
}

// ---------------- launch ----------------
extern "C" void kernel_launch(void* const* d_in, const int* in_sizes, int n_in,
                              void* d_out, int out_size) {
    const float* agent = (const float*)d_in[0];
    const float* lanec = (const float*)d_in[1];
    const float* nghl  = (const float*)d_in[2];
    const float* ngh   = (const float*)d_in[3];
    const int*   label = (const int*)d_in[4];
    const float* W1    = (const float*)d_in[5];
    const float* b1    = (const float*)d_in[6];
    const float* W2    = (const float*)d_in[7];
    const float* b2    = (const float*)d_in[8];
    float* out = (float*)d_out;

    cudaFuncSetAttribute(agemm_kernel, cudaFuncAttributeMaxDynamicSharedMemorySize, G1_SMEM);
    cudaFuncSetAttribute(gemm1_kernel, cudaFuncAttributeMaxDynamicSharedMemorySize, G1_SMEM);
    cudaFuncSetAttribute(gemm2_kernel, cudaFuncAttributeMaxDynamicSharedMemorySize, G2_SMEM);

    w1t_kernel<<<dim3(64, 16), dim3(32, 8)>>>(W1);
    prep_rows_kernel<<<40960, 128>>>(lanec, nghl, ngh, agent, label, out);
    prep2_kernel<<<480, 256>>>(W2, b2, out);
    agemm_kernel<<<dim3(2, 32), 256, G1_SMEM>>>(b1);
    gemm1_kernel<<<dim3(2, 320), 256, G1_SMEM>>>();
    gemm2_kernel<<<dim3(32, 4), 256, G2_SMEM>>>(out);
}